// round 11
// baseline (speedup 1.0000x reference)
#include <cuda_runtime.h>
#include <cstdint>

// C51 categorical projection — scatter scan + double-buffered bulk-async
// (TMA) pipeline. Each CTA processes ~7 tiles: scan(t) overlaps load(t+G)
// and store(t-G). Buffer reuse gated by cp.async.bulk.wait_group.READ
// (smem read-out only, not DRAM completion).
//
// b(j) = clamp(c + s*j, 0, 50), s = 0.99*nd, c = 2.5*(reward + 10 - 10*s).
// floor(b) nondecreasing, step in {0,1}: two live bins in registers, bin
// emitted with one predicated STS when k advances.
//
// Packed rows (stride 51): smem tile byte-identical to gmem tile -> whole-tile
// bulk copies; row-owner access conflict-free (bank (19t+j)%32, 19 coprime 32).

constexpr int A           = 51;
constexpr int RPB         = 128;
constexpr int TILE_FLOATS = RPB * A;              // 6528
constexpr int TILE_BYTES  = TILE_FLOATS * 4;      // 26112
constexpr int SMEM_BYTES  = 32 + 2 * TILE_BYTES;  // 2 mbars + 2 tiles
constexpr int GRID_MAX    = 148 * 4;              // 4 CTAs/SM resident

__device__ __forceinline__ uint32_t smem_u32(const void* p) {
    uint32_t a;
    asm("{ .reg .u64 t; cvta.to.shared.u64 t, %1; cvt.u32.u64 %0, t; }"
        : "=r"(a) : "l"(p));
    return a;
}

__device__ __forceinline__ void mbar_wait(uint32_t mbar_a, uint32_t phase) {
    uint32_t done = 0;
    while (!done) {
        asm volatile(
            "{ .reg .pred p; "
            "  mbarrier.try_wait.parity.shared.b64 p, [%1], %2; "
            "  selp.b32 %0, 1, 0, p; }"
            : "=r"(done) : "r"(mbar_a), "r"(phase) : "memory");
    }
}

__device__ __forceinline__ void issue_load(uint32_t dst_a, const float* src,
                                           uint32_t mbar_a) {
    asm volatile("mbarrier.arrive.expect_tx.shared.b64 _, [%0], %1;"
                 :: "r"(mbar_a), "r"((uint32_t)TILE_BYTES) : "memory");
    asm volatile(
        "cp.async.bulk.shared::cluster.global.mbarrier::complete_tx::bytes "
        "[%0], [%1], %2, [%3];"
        :: "r"(dst_a), "l"(src), "r"((uint32_t)TILE_BYTES), "r"(mbar_a)
        : "memory");
}

__global__ __launch_bounds__(RPB, 4)
void cat_proj_kernel(const float* __restrict__ reward,
                     const float* __restrict__ probs,
                     const float* __restrict__ not_done,
                     float* __restrict__ out,
                     int bs, int ntiles)
{
    extern __shared__ float smraw[];              // 16B-aligned
    uint64_t* mbars = (uint64_t*)smraw;           // [0,16)
    float* tp0 = smraw + 8;                       // tile 0 (32B offset)
    float* tp1 = tp0 + TILE_FLOATS;               // tile 1

    const int tid = threadIdx.x;
    const uint32_t mb0 = smem_u32(mbars);
    const uint32_t mb1 = smem_u32(mbars + 1);
    const uint32_t ta0 = smem_u32(tp0);
    const uint32_t ta1 = smem_u32(tp1);

    if (tid == 0) {
        asm volatile("mbarrier.init.shared.b64 [%0], 1;" :: "r"(mb0) : "memory");
        asm volatile("mbarrier.init.shared.b64 [%0], 1;" :: "r"(mb1) : "memory");
    }
    __syncthreads();

    int ph0 = 0, ph1 = 0;

    // ── prologue: issue load of the first tile into buf0
    {
        int t = blockIdx.x;
        if (t < ntiles && tid == 0) {
            if (min(RPB, bs - t * RPB) == RPB)
                issue_load(ta0, probs + (size_t)t * RPB * A, mb0);
        }
    }

    int i = 0;
    for (int t = blockIdx.x; t < ntiles; t += gridDim.x, i++) {
        const int buf  = i & 1;
        const int rbase = t * RPB;
        const int rows  = min(RPB, bs - rbase);
        const bool full = (rows == RPB);
        float*   tile   = buf ? tp1 : tp0;
        uint32_t tile_a = buf ? ta1 : ta0;
        uint32_t mb     = buf ? mb1 : mb0;

        // per-row scalars (overlap with in-flight TMA)
        const int grow = rbase + tid;
        float rw = 0.0f, nd = 0.0f;
        if (grow < bs) { rw = reward[grow]; nd = not_done[grow]; }

        // ── issue NEXT tile load into the other buffer (after its previous
        //    store has been read out of smem)
        if (tid == 0) {
            int tn = t + gridDim.x;
            if (tn < ntiles && min(RPB, bs - tn * RPB) == RPB) {
                asm volatile("cp.async.bulk.wait_group.read 0;" ::: "memory");
                issue_load(buf ? ta0 : ta1,
                           probs + (size_t)tn * RPB * A,
                           buf ? mb0 : mb1);
            }
        }

        // ── wait for this tile's data
        if (full) {
            int ph = buf ? ph1 : ph0;
            mbar_wait(mb, (uint32_t)ph);
            if (buf) ph1 ^= 1; else ph0 ^= 1;
        } else {
            for (int q = tid; q < rows * A; q += RPB)
                tile[q] = probs[(size_t)rbase * A + q];
            __syncthreads();
        }

        // ── scan (one thread per row), in place
        if (tid < rows) {
            float* row = tile + tid * A;

            float pv[A];
            #pragma unroll
            for (int j = 0; j < A; j++) pv[j] = row[j];
            #pragma unroll
            for (int j = 0; j < A; j++) row[j] = 0.0f;

            const float s = 0.99f * nd;
            const float c = 2.5f * (rw + 10.0f - 10.0f * s);

            float b  = fminf(fmaxf(c, 0.0f), 50.0f);
            float lf = floorf(b);
            int   k  = (int)lf;
            float wu = (b - lf) * pv[0];
            float aK  = pv[0] - wu;
            float aK1 = wu;

            #pragma unroll
            for (int j = 1; j < A; j++) {
                b  = fminf(fmaxf(fmaf(s, (float)j, c), 0.0f), 50.0f);
                lf = floorf(b);
                int li = (int)lf;             // in {k, k+1}
                wu = (b - lf) * pv[j];
                float wl = pv[j] - wu;

                bool adv = (li != k);
                if (adv) row[k] = aK;         // predicated single STS
                aK  = adv ? aK1  : aK;
                aK1 = adv ? 0.0f : aK1;
                k   = li;

                aK  += wl;
                aK1 += wu;
            }
            int k1 = k + 1; if (k1 > A - 1) k1 = A - 1;
            row[k1] = aK1;                    // if k==50, aK1==0: benign
            row[k]  = aK;
        }
        __syncthreads();

        // ── store this tile (async; drained before this buffer's next reuse)
        float* gdst = out + (size_t)rbase * A;
        if (full) {
            if (tid == 0) {
                asm volatile("fence.proxy.async.shared::cta;" ::: "memory");
                asm volatile(
                    "cp.async.bulk.global.shared::cta.bulk_group [%0], [%1], %2;"
                    :: "l"(gdst), "r"(tile_a), "r"((uint32_t)TILE_BYTES)
                    : "memory");
                asm volatile("cp.async.bulk.commit_group;" ::: "memory");
            }
        } else {
            for (int q = tid; q < rows * A; q += RPB)
                gdst[q] = tile[q];
        }
        // NOTE: no wait here; next reuse of this buffer waits on read-drain,
        // __syncthreads above orders scan vs store issue.
    }

    // ── epilogue: make sure all stores are fully complete before exit
    if (tid == 0)
        asm volatile("cp.async.bulk.wait_group 0;" ::: "memory");
}

extern "C" void kernel_launch(void* const* d_in, const int* in_sizes, int n_in,
                              void* d_out, int out_size)
{
    const float* reward   = (const float*)d_in[0];
    const float* probs    = (const float*)d_in[1];
    const float* not_done = (const float*)d_in[2];
    float* out = (float*)d_out;

    const int bs     = in_sizes[0];
    const int ntiles = (bs + RPB - 1) / RPB;
    const int grid   = ntiles < GRID_MAX ? ntiles : GRID_MAX;

    cudaFuncSetAttribute(cat_proj_kernel,
                         cudaFuncAttributeMaxDynamicSharedMemorySize,
                         SMEM_BYTES);
    cat_proj_kernel<<<grid, RPB, SMEM_BYTES>>>(reward, probs, not_done, out,
                                               bs, ntiles);
}

// round 12
// speedup vs baseline: 1.1020x; 1.1020x over previous
#include <cuda_runtime.h>
#include <cstdint>

// C51 categorical projection — scatter scan + 1D bulk-async (TMA) tile I/O,
// IN-PLACE smem tile, 64-row tiles so ~13 CTAs/SM run independent
// load/scan/store chains (latency-overlap via chain count, not intra-CTA
// pipelining — R11 showed the double-buffer variant loses to more chains).
//
// b(j) = clamp(c + s*j, 0, 50), s = 0.99*nd, c = 2.5*(reward + 10 - 10*s).
// floor(b) nondecreasing, step in {0,1}: two live bins in registers, bin
// emitted with one predicated STS when k advances.
//
// Tile rows are PACKED (stride 51): smem tile is byte-identical to the gmem
// tile, so stage-in and copy-out are single cp.async.bulk copies. Packed rows
// are conflict-free for row-owner access: word 51*t + j -> bank (19t+j)%32,
// gcd(19,32)=1 => lane bijection.

constexpr int A           = 51;
constexpr int RPB         = 64;
constexpr int TILE_FLOATS = RPB * A;            // 3264
constexpr int TILE_BYTES  = TILE_FLOATS * 4;    // 13056 (multiple of 16)
constexpr int SMEM_BYTES  = 16 + TILE_BYTES;    // mbar pad + tile

__device__ __forceinline__ uint32_t smem_u32(const void* p) {
    uint32_t a;
    asm("{ .reg .u64 t; cvta.to.shared.u64 t, %1; cvt.u32.u64 %0, t; }"
        : "=r"(a) : "l"(p));
    return a;
}

__global__ __launch_bounds__(RPB, 13)
void cat_proj_kernel(const float* __restrict__ reward,
                     const float* __restrict__ probs,
                     const float* __restrict__ not_done,
                     float* __restrict__ out,
                     int bs)
{
    extern __shared__ float smraw[];            // 16B-aligned
    uint64_t* mbar = (uint64_t*)smraw;          // [0,8)
    float*    tile = smraw + 4;                 // packed [RPB][51]

    const int tid   = threadIdx.x;
    const int rbase = blockIdx.x * RPB;
    const int rows  = min(RPB, bs - rbase);
    const bool full = (rows == RPB);

    const uint32_t mbar_a = smem_u32(mbar);
    const uint32_t tile_a = smem_u32(tile);

    if (tid == 0)
        asm volatile("mbarrier.init.shared.b64 [%0], 1;" :: "r"(mbar_a) : "memory");
    __syncthreads();

    // ── stage-in: one bulk async copy (full blocks), scalar fallback (tail)
    const float* gsrc = probs + (size_t)rbase * A;
    if (full) {
        if (tid == 0) {
            asm volatile("mbarrier.arrive.expect_tx.shared.b64 _, [%0], %1;"
                         :: "r"(mbar_a), "r"((uint32_t)TILE_BYTES) : "memory");
            asm volatile(
                "cp.async.bulk.shared::cluster.global.mbarrier::complete_tx::bytes "
                "[%0], [%1], %2, [%3];"
                :: "r"(tile_a), "l"(gsrc), "r"((uint32_t)TILE_BYTES), "r"(mbar_a)
                : "memory");
        }
    } else {
        for (int i = tid; i < rows * A; i += RPB) tile[i] = gsrc[i];
        __syncthreads();
    }

    // ── overlap with the TMA load: per-row scalars
    const int grow = rbase + tid;
    float rw = 0.0f, nd = 0.0f;
    if (grow < bs) { rw = reward[grow]; nd = not_done[grow]; }

    // ── wait for the tile
    if (full) {
        uint32_t done = 0;
        while (!done) {
            asm volatile(
                "{ .reg .pred p; "
                "  mbarrier.try_wait.parity.shared.b64 p, [%1], %2; "
                "  selp.b32 %0, 1, 0, p; }"
                : "=r"(done) : "r"(mbar_a), "r"(0u) : "memory");
        }
    }

    // ── scan (one thread per row), in place
    if (tid < rows) {
        float* row = tile + tid * A;

        // prefetch own row to registers
        float pv[A];
        #pragma unroll
        for (int j = 0; j < A; j++) pv[j] = row[j];

        // zero own row in place (reads done)
        #pragma unroll
        for (int j = 0; j < A; j++) row[j] = 0.0f;

        const float s = 0.99f * nd;
        const float c = 2.5f * (rw + 10.0f - 10.0f * s);

        float b  = fminf(fmaxf(c, 0.0f), 50.0f);
        float lf = floorf(b);
        int   k  = (int)lf;
        float wu = (b - lf) * pv[0];
        float aK  = pv[0] - wu;
        float aK1 = wu;

        #pragma unroll
        for (int j = 1; j < A; j++) {
            b  = fminf(fmaxf(fmaf(s, (float)j, c), 0.0f), 50.0f);
            lf = floorf(b);
            int li = (int)lf;                 // in {k, k+1}
            wu = (b - lf) * pv[j];
            float wl = pv[j] - wu;

            bool adv = (li != k);
            if (adv) row[k] = aK;             // predicated single STS
            aK  = adv ? aK1  : aK;
            aK1 = adv ? 0.0f : aK1;
            k   = li;

            aK  += wl;
            aK1 += wu;
        }
        int k1 = k + 1; if (k1 > A - 1) k1 = A - 1;
        row[k1] = aK1;                         // if k==50, aK1==0: benign
        row[k]  = aK;
    }
    __syncthreads();

    // ── copy-out: one bulk async store (full blocks), scalar fallback (tail)
    float* gdst = out + (size_t)rbase * A;
    if (full) {
        if (tid == 0) {
            asm volatile("fence.proxy.async.shared::cta;" ::: "memory");
            asm volatile(
                "cp.async.bulk.global.shared::cta.bulk_group [%0], [%1], %2;"
                :: "l"(gdst), "r"(tile_a), "r"((uint32_t)TILE_BYTES) : "memory");
            asm volatile("cp.async.bulk.commit_group;" ::: "memory");
            asm volatile("cp.async.bulk.wait_group 0;" ::: "memory");
        }
    } else {
        for (int i = tid; i < rows * A; i += RPB) gdst[i] = tile[i];
    }
}

extern "C" void kernel_launch(void* const* d_in, const int* in_sizes, int n_in,
                              void* d_out, int out_size)
{
    const float* reward   = (const float*)d_in[0];
    const float* probs    = (const float*)d_in[1];
    const float* not_done = (const float*)d_in[2];
    float* out = (float*)d_out;

    const int bs   = in_sizes[0];
    const int grid = (bs + RPB - 1) / RPB;

    cudaFuncSetAttribute(cat_proj_kernel,
                         cudaFuncAttributeMaxDynamicSharedMemorySize,
                         SMEM_BYTES);
    cat_proj_kernel<<<grid, RPB, SMEM_BYTES>>>(reward, probs, not_done, out, bs);
}